// round 4
// baseline (speedup 1.0000x reference)
#include <cuda_runtime.h>
#include <math.h>

#define DD 31
#define DIMV 32
#define TSTRIDE 36   // floats per s_T row (32 data + 4 pad, 144B = 16B aligned)
#define MARGIN 0.85f

#define ASU64(x)  (*reinterpret_cast<unsigned long long*>(&(x)))
#define ASU64C(x) (*reinterpret_cast<const unsigned long long*>(&(x)))

// ---- packed fp32x2 (Blackwell) ----
__device__ __forceinline__ float2 ffma2(float2 a, float2 b, float2 c) {
    float2 d;
    asm("fma.rn.f32x2 %0, %1, %2, %3;"
        : "=l"(ASU64(d)) : "l"(ASU64C(a)), "l"(ASU64C(b)), "l"(ASU64C(c)));
    return d;
}
__device__ __forceinline__ float2 fadd2(float2 a, float2 b) {
    float2 d;
    asm("add.rn.f32x2 %0, %1, %2;" : "=l"(ASU64(d)) : "l"(ASU64C(a)), "l"(ASU64C(b)));
    return d;
}
__device__ __forceinline__ float2 fsub2(float2 a, float2 b) {
    float2 d;
    asm("sub.rn.f32x2 %0, %1, %2;" : "=l"(ASU64(d)) : "l"(ASU64C(a)), "l"(ASU64C(b)));
    return d;
}
// duplicate scalar into an aligned 64-bit pair (single MOV64)
__device__ __forceinline__ float2 dup2(float x) {
    float2 d;
    asm("mov.b64 %0, {%1, %1};" : "=l"(ASU64(d)) : "f"(x));
    return d;
}
// one 16B shared load -> two aligned float2 pairs, zero repacking
__device__ __forceinline__ void lds_2x64(unsigned addr, float2& a, float2& b) {
    asm("ld.shared.v2.b64 {%0, %1}, [%2];"
        : "=l"(ASU64(a)), "=l"(ASU64(b)) : "r"(addr));
}
__device__ __forceinline__ unsigned sptr(const void* p) {
    return (unsigned)__cvta_generic_to_shared(p);
}

__device__ __forceinline__ float gelu_exact(float x) {
    return 0.5f * x * (1.0f + erff(x * 0.70710678118654752440f));
}

__device__ __forceinline__ float warp_sum(float v) {
#pragma unroll
    for (int o = 16; o; o >>= 1) v += __shfl_xor_sync(0xffffffffu, v, o);
    return v;
}

__global__ __launch_bounds__(256, 2)
void hypernet_kernel(const int* __restrict__ g_u, const int* __restrict__ g_r,
                     const int* __restrict__ g_v, const float* __restrict__ emb,
                     const float* __restrict__ bias_head, const float* __restrict__ bias_tail,
                     const float* __restrict__ head_rot_w, const float* __restrict__ head_boost_w,
                     const float* __restrict__ tail_rot_w, const float* __restrict__ tail_boost_w,
                     float* __restrict__ out, int N) {
    __shared__ __align__(16) float s_wt[DD][DIMV];      // gelu'd tail Householder rows, col31=0
    __shared__ __align__(16) float s_wh[DD][DIMV];      // gelu'd head rows; [i][31] = 2/n2
    __shared__ __align__(16) float s_T[DIMV][TSTRIDE];  // fused rot+boost matrix, row=input dim
    __shared__ __align__(16) float s_th[DIMV];          // transformed head vector (time at [0])
    __shared__ __align__(16) float s_ro[DIMV];          // tail rapidity (31) + pad 0
    __shared__ float s_beta[DD];                        // -2/n2 per tail reflection
    __shared__ float s_par[4];                          // zeta_t, kappa_t, tanh(bias_head[u])

    const int b    = blockIdx.x;
    const int tid  = threadIdx.x;
    const int lane = tid & 31;
    const int wid  = tid >> 5;
    const int rb   = g_r[b];

    // ---------------- Phase A: gelu both rotation tables ----------------
    const float* tw = tail_rot_w + (long)rb * (DD * DD);
    const float* hw = head_rot_w + (long)rb * (DD * DD);
    for (int k = tid; k < DD * DIMV; k += 256) {
        int i = k >> 5, j = k & 31;
        s_wt[i][j] = (j < DD) ? gelu_exact(tw[i * DD + j]) : 0.f;
        s_wh[i][j] = (j < DD) ? gelu_exact(hw[i * DD + j]) : 0.f;
    }
    __syncthreads();

    // ---------------- Phase A2: boost params + row norms + head bias ----------------
    if (wid == 2) {
        float ro = (lane < DD) ? tanhf(tail_boost_w[(long)rb * DD + lane]) * (1.0f / DIMV) : 0.f;
        s_ro[lane] = ro;
        float v2 = warp_sum(ro * ro);
        if (lane == 0) {
            float zeta = 1.0f / (sqrtf(1.0f - v2) + 1e-8f);
            s_par[0] = zeta;
            s_par[1] = (zeta - 1.0f) / (v2 + 1e-9f);
        }
    } else if (wid == 3) {
#pragma unroll 1
        for (int i = 0; i < DD; i++) {
            float w  = (lane < DD) ? s_wt[i][lane] : 0.f;
            float n2 = warp_sum(w * w);
            if (lane == 0) s_beta[i] = -2.0f / n2;
        }
    } else if (wid == 4) {
#pragma unroll 1
        for (int i = 0; i < DD; i++) {
            float w  = (lane < DD) ? s_wh[i][lane] : 0.f;
            float n2 = warp_sum(w * w);
            if (lane == 0) s_wh[i][DD] = 2.0f / n2;
        }
    } else if (wid == 5) {
        if (lane == 0) s_par[2] = tanhf(bias_head[g_u[b]]);
    }
    __syncthreads();

    // ---------------- Build (warp 0): P = Q^T column-per-lane, fold boost into s_T ----
    if (wid == 0) {
        const float zt = s_par[0];
        const float kp = s_par[1];
        if (lane < DD) {
            // lane owns column `lane` of P = H31...H1  (=> row `lane` of Q)
            float2 P2[16];
#pragma unroll
            for (int k = 0; k < 16; k++)
                P2[k] = make_float2((2 * k == lane) ? 1.f : 0.f,
                                    (2 * k + 1 == lane) ? 1.f : 0.f);
            const unsigned wbase = sptr(&s_wt[0][0]);
#pragma unroll 1
            for (int i = 0; i < DD; i++) {
                float2 w2[16];
#pragma unroll
                for (int q = 0; q < 8; q++)
                    lds_2x64(wbase + (unsigned)i * (DIMV * 4) + q * 16, w2[2 * q], w2[2 * q + 1]);
                float2 za = make_float2(0.f, 0.f), zb = za, zc = za, zd = za;
#pragma unroll
                for (int k = 0; k < 16; k += 4) {
                    za = ffma2(w2[k], P2[k], za);
                    zb = ffma2(w2[k + 1], P2[k + 1], zb);
                    zc = ffma2(w2[k + 2], P2[k + 2], zc);
                    zd = ffma2(w2[k + 3], P2[k + 3], zd);
                }
                float2 zs = fadd2(fadd2(za, zb), fadd2(zc, zd));
                float z = zs.x + zs.y;             // w . P[:,lane]
                float g = s_beta[i] * z;           // -2/n2 * z
                float2 g2 = dup2(g);
#pragma unroll
                for (int k = 0; k < 16; k++) P2[k] = ffma2(g2, w2[k], P2[k]);
            }
            // s_c = Q[lane] . ro  (in-lane: P column = Q row)
            float2 ro2[16];
            const unsigned robase = sptr(&s_ro[0]);
#pragma unroll
            for (int q = 0; q < 8; q++) lds_2x64(robase + q * 16, ro2[2 * q], ro2[2 * q + 1]);
            float2 sa = make_float2(0.f, 0.f), sb = sa, sc2 = sa, sd = sa;
#pragma unroll
            for (int k = 0; k < 16; k += 4) {
                sa = ffma2(ro2[k], P2[k], sa);
                sb = ffma2(ro2[k + 1], P2[k + 1], sb);
                sc2 = ffma2(ro2[k + 2], P2[k + 2], sc2);
                sd = ffma2(ro2[k + 3], P2[k + 3], sd);
            }
            float2 ss = fadd2(fadd2(sa, sb), fadd2(sc2, sd));
            float s = ss.x + ss.y;

            // write s_T row (lane+1): [ -zeta*s, Q[lane][m] + kappa*ro_m*s  for m=0..30 ]
            float ks = kp * s;
            float2 ks2 = dup2(ks);
            float* row = &s_T[lane + 1][0];
            row[0] = -zt * s;
#pragma unroll
            for (int k = 0; k < 16; k++) {
                float2 val = ffma2(ks2, ro2[k], P2[k]);
                row[1 + 2 * k] = val.x;
                if (2 * k + 1 < DD) row[2 + 2 * k] = val.y;
            }
        } else {
            // lane 31: s_T row 0 = [ zeta, -zeta*ro_0 .. -zeta*ro_30 ]
            float* row = &s_T[0][0];
            row[0] = zt;
#pragma unroll
            for (int j = 0; j < DD; j++) row[1 + j] = -zt * s_ro[j];
        }
    }
    // ---------------- Head chain (warp 1, concurrent with build) ----------------
    else if (wid == 1) {
        float c = emb[(long)g_u[b] * DIMV + lane];
#pragma unroll 1
        for (int i = 0; i < DD; i++) {
            float w   = (lane >= 1) ? s_wh[i][lane - 1] : 0.f;
            float sc  = s_wh[i][DD];
            float dot = warp_sum(c * w);
            c = fmaf(-sc * dot, w, c);
        }
        float rh   = (lane >= 1) ? tanhf(head_boost_w[(long)rb * DD + lane - 1]) * (1.0f / DIMV) : 0.f;
        float v2   = warp_sum(rh * rh);
        float zeta = 1.0f / (sqrtf(1.0f - v2) + 1e-8f);
        float coef = (zeta - 1.0f) / (v2 + 1e-9f);
        float tval = __shfl_sync(0xffffffffu, c, 0);
        float dotb = warp_sum(c * rh);
        float res;
        if (lane == 0) res = zeta * tval - zeta * dotb;
        else           res = -zeta * tval * rh + c + coef * rh * dotb;
        s_th[lane] = res;
    }
    __syncthreads();

    // ---------------- Phase C: y = x^T . s_T (matvec), then Lorentz distance ----------
    const float tbh = s_par[2];
    const unsigned tbase  = sptr(&s_T[0][0]);
    const unsigned thbase = sptr(&s_th[0]);

    for (int n = tid; n < N; n += 256) {
        const int vi = g_v[(long)b * N + n];
        float4 xq[8];
        const float4* ep = (const float4*)(emb + (long)vi * DIMV);
#pragma unroll
        for (int q = 0; q < 8; q++) xq[q] = ep[q];
        const float btail = bias_tail[vi];

        float2 y[16];
#pragma unroll
        for (int k = 0; k < 16; k++) y[k] = make_float2(0.f, 0.f);

#pragma unroll
        for (int q8 = 0; q8 < 8; q8++) {
            const float xs0 = xq[q8].x, xs1 = xq[q8].y, xs2 = xq[q8].z, xs3 = xq[q8].w;
#pragma unroll
            for (int c4 = 0; c4 < 4; c4++) {
                const int d = q8 * 4 + c4;
                const float xd = (c4 == 0) ? xs0 : (c4 == 1) ? xs1 : (c4 == 2) ? xs2 : xs3;
                const float2 x2 = dup2(xd);
                const unsigned rowaddr = tbase + (unsigned)d * (TSTRIDE * 4);
#pragma unroll
                for (int q = 0; q < 8; q++) {
                    float2 p0, p1;
                    lds_2x64(rowaddr + q * 16, p0, p1);
                    y[2 * q]     = ffma2(x2, p0, y[2 * q]);
                    y[2 * q + 1] = ffma2(x2, p1, y[2 * q + 1]);
                }
            }
        }

        // distance: sum (y_c - th_c)^2 - 2*(y_0 - th_0)^2
        float2 accA = make_float2(0.f, 0.f), accB = accA;
#pragma unroll
        for (int k = 0; k < 8; k++) {
            float2 t0, t1;
            lds_2x64(thbase + k * 16, t0, t1);
            float2 e0 = fsub2(y[2 * k], t0);
            float2 e1 = fsub2(y[2 * k + 1], t1);
            accA = ffma2(e0, e0, accA);
            accB = ffma2(e1, e1, accB);
        }
        const float2 acc = fadd2(accA, accB);
        const float dd0  = y[0].x - s_th[0];
        const float mkv  = (acc.x + acc.y) - 2.f * dd0 * dd0;

        out[(long)b * N + n] = MARGIN - mkv + tbh + tanhf(btail);
    }
}

extern "C" void kernel_launch(void* const* d_in, const int* in_sizes, int n_in,
                              void* d_out, int out_size) {
    const int*   u   = (const int*)d_in[0];
    const int*   r   = (const int*)d_in[1];
    const int*   v   = (const int*)d_in[2];
    const float* emb = (const float*)d_in[3];
    const float* bh  = (const float*)d_in[4];
    const float* bt  = (const float*)d_in[5];
    const float* hrw = (const float*)d_in[6];
    const float* hbw = (const float*)d_in[7];
    const float* trw = (const float*)d_in[8];
    const float* tbw = (const float*)d_in[9];
    float* out = (float*)d_out;

    const int B = in_sizes[0];
    const int N = in_sizes[2] / B;

    hypernet_kernel<<<B, 256>>>(u, r, v, emb, bh, bt, hrw, hbw, trw, tbw, out, N);
}